// round 12
// baseline (speedup 1.0000x reference)
#include <cuda_runtime.h>
#include <cuda_bf16.h>
#include <cstdint>

// fast softplus for small |x| (here |x| <~ 2, far from exp overflow at 88):
// log(1 + exp(x)); compiles to FMUL+MUFU.EX2+FADD+MUFU.LG2+FMUL
__device__ __forceinline__ float softplus_f(float x) {
    return __logf(1.0f + __expf(x));
}

__device__ __forceinline__ uint32_t smem_u32(const void* p) {
    return (uint32_t)__cvta_generic_to_shared(p);
}

#define MBAR_INIT(addr, cnt) \
    asm volatile("mbarrier.init.shared.b64 [%0], %1;" :: "r"(addr), "r"(cnt) : "memory")
#define MBAR_EXPECT_TX(addr, bytes) \
    asm volatile("mbarrier.arrive.expect_tx.shared.b64 _, [%0], %1;" :: "r"(addr), "r"(bytes) : "memory")
#define BULK_G2S(dst_smem, src_gmem, nbytes, bar) \
    asm volatile("cp.async.bulk.shared::cta.global.mbarrier::complete_tx::bytes [%0], [%1], %2, [%3];" \
                 :: "r"(dst_smem), "l"(src_gmem), "r"(nbytes), "r"(bar) : "memory")

__device__ __forceinline__ void mbar_wait_parity(uint32_t bar, uint32_t parity) {
    uint32_t done;
    asm volatile(
        "{\n\t.reg .pred p;\n\t"
        "mbarrier.try_wait.parity.acquire.cta.shared::cta.b64 p, [%1], %2;\n\t"
        "selp.b32 %0, 1, 0, p;\n\t}"
        : "=r"(done) : "r"(bar), "r"(parity) : "memory");
    while (!done) {
        asm volatile(
            "{\n\t.reg .pred p;\n\t"
            "mbarrier.try_wait.parity.acquire.cta.shared::cta.b64 p, [%1], %2, 0x989680;\n\t"
            "selp.b32 %0, 1, 0, p;\n\t}"
            : "=r"(done) : "r"(bar), "r"(parity) : "memory");
    }
}

// One CTA per batch row, 4 CTAs/SM (48KB smem). Row streamed through RING=2
// x 1536-elem SMEM buffers via cp.async.bulk. 4 elems/thread per chunk,
// single __syncthreads per chunk. Hot path: f = I * fmaf(h, B, A) with
// h = log(1+exp(w1e0*I + w1e1*Temp + be1)).
template <int NTHREADS, int CELEMS, int RING>
__global__ __launch_bounds__(NTHREADS, 4)
void soc_kernel(const float4* __restrict__ X,       // (B, T, 4)
                const float*  __restrict__ SC,      // (B, 4)
                const float*  __restrict__ W1i, const float* __restrict__ b1i,
                const float*  __restrict__ W2i, const float* __restrict__ b2i,
                const float*  __restrict__ W1e, const float* __restrict__ b1e,
                const float*  __restrict__ W2e, const float* __restrict__ b2e,
                float* __restrict__ out,            // (B, T)
                int T)
{
    extern __shared__ __align__(128) float4 xbuf[];    // RING * CELEMS float4
    __shared__ __align__(8) uint64_t mbar[RING];
    __shared__ float warp_tot[2][32];                  // double-buffered
    __shared__ float2 bnd[2];                          // (ts, f) carry, double-buffered

    const int b    = blockIdx.x;
    const int tid  = threadIdx.x;
    const int lane = tid & 31;
    const int warp = tid >> 5;
    constexpr int NW = NTHREADS / 32;                  // 12
    const unsigned FULL = 0xFFFFFFFFu;
    const long long rowbase = (long long)b * (long long)T;
    const int nchunks = (T + CELEMS - 1) / CELEMS;

    if (tid == 0) {
        #pragma unroll
        for (int r = 0; r < RING; r++)
            MBAR_INIT(smem_u32(&mbar[r]), 1);
    }
    __syncthreads();

    // prime the ring
    if (tid == 0) {
        const int prime = (nchunks < RING) ? nchunks : RING;
        for (int c = 0; c < prime; c++) {
            const int lim = min(CELEMS, T - c * CELEMS);
            const uint32_t nbytes = (uint32_t)lim * 16u;
            const uint32_t bar = smem_u32(&mbar[c]);
            MBAR_EXPECT_TX(bar, nbytes);
            BULK_G2S(smem_u32(&xbuf[c * CELEMS]),
                     (const void*)(X + rowbase + (long long)c * CELEMS),
                     nbytes, bar);
        }
    }

    // Per-batch scalars (overlaps with TMA flight)
    const float w1e0 = W1e[0], w1e1 = W1e[1];
    const float be1  = b1e[0];
    const float scale = SC[b * 4 + 1] / (3600.0f * SC[b * 4 + 0]);
    const float A = scale * (1.0f + b2e[0]);   // f = I * (A + B*h)
    const float Bc = scale * W2e[0];

    float base = 0.0f;   // SOC_init + running cumsum carry (set at c==0)

    for (int c = 0; c < nchunks; c++) {
        const int slot = c % RING;
        mbar_wait_parity(smem_u32(&mbar[slot]), (uint32_t)((c / RING) & 1));

        const float4* xb = &xbuf[slot * CELEMS];
        const int lim = min(CELEMS, T - c * CELEMS);
        const int s = tid * 4;
        const int cb = c & 1;

        if (c == 0) {
            // SOC_init from t=0 features (broadcast LDS); exact softplus form
            float4 x0 = xb[0];
            float z0 = x0.y * W1i[0] + x0.z * W1i[1] + x0.w * W1i[2]
                     + SC[b * 4 + 2] * W1i[3] + b1i[0];
            float h0 = fmaxf(z0, 0.0f) + __logf(1.0f + __expf(-fabsf(z0)));
            base = SC[b * 4 + 3] * (1.0f + (h0 * W2i[0] + b2i[0]));
        }

        float i0 = 0.f, i1 = 0.f, i2 = 0.f, i3 = 0.f;
        float ts3 = 0.f, f3 = 0.f;             // last-elem (ts,f) for shfl / bnd

        if (s + 3 < lim) {
            float4 v0 = xb[s + 0];
            float4 v1 = xb[s + 1];
            float4 v2 = xb[s + 2];
            float4 v3 = xb[s + 3];
            float h0e = softplus_f(fmaf(v0.y, w1e0, fmaf(v0.z, w1e1, be1)));
            float h1e = softplus_f(fmaf(v1.y, w1e0, fmaf(v1.z, w1e1, be1)));
            float h2e = softplus_f(fmaf(v2.y, w1e0, fmaf(v2.z, w1e1, be1)));
            float h3e = softplus_f(fmaf(v3.y, w1e0, fmaf(v3.z, w1e1, be1)));
            float f0 = v0.y * fmaf(h0e, Bc, A);
            float f1 = v1.y * fmaf(h1e, Bc, A);
            float f2 = v2.y * fmaf(h2e, Bc, A);
            f3       = v3.y * fmaf(h3e, Bc, A);
            ts3 = v3.x;

            float pts = __shfl_up_sync(FULL, ts3, 1);
            float pf  = __shfl_up_sync(FULL, f3, 1);
            if (lane == 0) {
                if (s > 0) {                   // cross-warp boundary: recompute
                    float4 vp = xb[s - 1];
                    float hp = softplus_f(fmaf(vp.y, w1e0, fmaf(vp.z, w1e1, be1)));
                    pts = vp.x;
                    pf  = vp.y * fmaf(hp, Bc, A);
                } else if (c > 0) {            // chunk boundary carry
                    float2 bc = bnd[cb];       // written by chunk c-1 pre-its-barrier
                    pts = bc.x; pf = bc.y;
                }
            }
            if (c > 0 || s > 0 || lane > 0)    // global t==0 has no increment
                i0 = (v0.x - pts) * pf;
            i1 = (v1.x - v0.x) * f0;
            i2 = (v2.x - v1.x) * f1;
            i3 = (v3.x - v2.x) * f2;
        } else {
            // tail path (rare)
            float pts = 0.f, pf = 0.f;
            bool havep = false;
            if (s < lim && (s > 0 || c > 0)) {
                if (s > 0) {
                    float4 vp = xb[s - 1];
                    float hp = softplus_f(fmaf(vp.y, w1e0, fmaf(vp.z, w1e1, be1)));
                    pts = vp.x;
                    pf  = vp.y * fmaf(hp, Bc, A);
                } else { float2 bc = bnd[cb]; pts = bc.x; pf = bc.y; }
                havep = true;
            }
            float acc[4] = {0.f, 0.f, 0.f, 0.f};
            for (int j = 0; j < 4; j++) {
                const int t = s + j;
                if (t < lim) {
                    float4 v = xb[t];
                    if (havep) acc[j] = (v.x - pts) * pf;
                    float h = softplus_f(fmaf(v.y, w1e0, fmaf(v.z, w1e1, be1)));
                    pts = v.x;
                    pf  = v.y * fmaf(h, Bc, A);
                    havep = true;
                    ts3 = pts; f3 = pf;
                }
            }
            i0 = acc[0]; i1 = acc[1]; i2 = acc[2]; i3 = acc[3];
        }

        const float p0 = i0;
        const float p1 = p0 + i1;
        const float p2 = p1 + i2;
        const float run = p2 + i3;

        // warp-inclusive scan of per-thread totals
        float v = run;
        #pragma unroll
        for (int d = 1; d < 32; d <<= 1) {
            float o = __shfl_up_sync(FULL, v, d);
            if (lane >= d) v += o;
        }
        if (lane == 31) warp_tot[cb][warp] = v;
        // boundary carry for NEXT chunk (double-buffered; ordered by sync below)
        if (s == ((lim - 1) & ~3)) bnd[cb ^ 1] = make_float2(ts3, f3);

        __syncthreads();                       // single barrier per chunk

        // refill the freed slot with chunk c+RING ASAP (all xb reads pre-sync)
        if (tid == NTHREADS - 1 && c + RING < nchunks) {
            const int cn = c + RING;
            const int nlim = min(CELEMS, T - cn * CELEMS);
            const uint32_t nbytes = (uint32_t)nlim * 16u;
            const uint32_t bar = smem_u32(&mbar[slot]);
            MBAR_EXPECT_TX(bar, nbytes);
            BULK_G2S(smem_u32(&xbuf[slot * CELEMS]),
                     (const void*)(X + rowbase + (long long)cn * CELEMS),
                     nbytes, bar);
        }

        // every warp redundantly scans the NW warp totals (no 2nd sync)
        float w = (lane < NW) ? warp_tot[cb][lane] : 0.0f;
        #pragma unroll
        for (int d = 1; d < NW; d <<= 1) {
            float o = __shfl_up_sync(FULL, w, d);
            if (lane >= d) w += o;
        }
        const float warp_off = (warp > 0) ? __shfl_sync(FULL, w, warp - 1) : 0.0f;
        const float total    = __shfl_sync(FULL, w, NW - 1);

        const float excl = base + warp_off + (v - run);

        // ---- write out (STG.128) ----
        if (s + 3 < lim) {
            float4 ov;
            ov.x = excl + p0;
            ov.y = excl + p1;
            ov.z = excl + p2;
            ov.w = excl + run;
            *reinterpret_cast<float4*>(out + rowbase + c * CELEMS + s) = ov;
        } else {
            const float pv[4] = {p0, p1, p2, run};
            for (int j = 0; j < 4; j++)
                if (s + j < lim) out[rowbase + c * CELEMS + s + j] = excl + pv[j];
        }

        base += total;
    }
}

extern "C" void kernel_launch(void* const* d_in, const int* in_sizes, int n_in,
                              void* d_out, int out_size)
{
    const float4* X  = (const float4*)d_in[0];   // (B, T, 4) fp32
    const float* SC  = (const float*)d_in[1];    // (B, 4)
    const float* W1i = (const float*)d_in[2];
    const float* b1i = (const float*)d_in[3];
    const float* W2i = (const float*)d_in[4];
    const float* b2i = (const float*)d_in[5];
    const float* W1e = (const float*)d_in[6];
    const float* b1e = (const float*)d_in[7];
    const float* W2e = (const float*)d_in[8];
    const float* b2e = (const float*)d_in[9];
    float* out = (float*)d_out;

    const int B = in_sizes[1] / 4;               // SC is (B,4)
    const int T = in_sizes[0] / (B * 4);         // X is (B,T,4)

    constexpr int NTH = 384, CEL = 1536, RING = 2;
    const int smem_bytes = RING * CEL * 16;      // 48 KB
    static bool attr_set = false;
    if (!attr_set) {
        cudaFuncSetAttribute(soc_kernel<NTH, CEL, RING>,
                             cudaFuncAttributeMaxDynamicSharedMemorySize, smem_bytes);
        attr_set = true;
    }
    soc_kernel<NTH, CEL, RING><<<B, NTH, smem_bytes>>>(
        X, SC, W1i, b1i, W2i, b2i, W1e, b1e, W2e, b2e, out, T);
}

// round 13
// speedup vs baseline: 1.0567x; 1.0567x over previous
#include <cuda_runtime.h>
#include <cuda_bf16.h>
#include <cstdint>

// fast softplus for small |x| (here |x| <~ 2, far from exp overflow at 88):
__device__ __forceinline__ float softplus_f(float x) {
    return __logf(1.0f + __expf(x));
}

__device__ __forceinline__ uint32_t smem_u32(const void* p) {
    return (uint32_t)__cvta_generic_to_shared(p);
}

#define MBAR_INIT(addr, cnt) \
    asm volatile("mbarrier.init.shared.b64 [%0], %1;" :: "r"(addr), "r"(cnt) : "memory")
#define MBAR_EXPECT_TX(addr, bytes) \
    asm volatile("mbarrier.arrive.expect_tx.shared.b64 _, [%0], %1;" :: "r"(addr), "r"(bytes) : "memory")
#define BULK_G2S(dst_smem, src_gmem, nbytes, bar) \
    asm volatile("cp.async.bulk.shared::cta.global.mbarrier::complete_tx::bytes [%0], [%1], %2, [%3];" \
                 :: "r"(dst_smem), "l"(src_gmem), "r"(nbytes), "r"(bar) : "memory")

__device__ __forceinline__ void mbar_wait_parity(uint32_t bar, uint32_t parity) {
    uint32_t done;
    asm volatile(
        "{\n\t.reg .pred p;\n\t"
        "mbarrier.try_wait.parity.acquire.cta.shared::cta.b64 p, [%1], %2;\n\t"
        "selp.b32 %0, 1, 0, p;\n\t}"
        : "=r"(done) : "r"(bar), "r"(parity) : "memory");
    while (!done) {
        asm volatile(
            "{\n\t.reg .pred p;\n\t"
            "mbarrier.try_wait.parity.acquire.cta.shared::cta.b64 p, [%1], %2, 0x989680;\n\t"
            "selp.b32 %0, 1, 0, p;\n\t}"
            : "=r"(done) : "r"(bar), "r"(parity) : "memory");
    }
}

// One CTA per batch row; 24KB smem/CTA -> up to 8 CTAs/SM so ALL 1024 CTAs
// are co-resident (single wave, no wave-transition TMA exposure). Row
// streamed through RING=2 x 768-elem SMEM buffers via cp.async.bulk.
// 4 elems/thread per chunk, single __syncthreads per chunk.
template <int NTHREADS, int CELEMS, int RING>
__global__ __launch_bounds__(NTHREADS, 8)
void soc_kernel(const float4* __restrict__ X,       // (B, T, 4)
                const float*  __restrict__ SC,      // (B, 4)
                const float*  __restrict__ W1i, const float* __restrict__ b1i,
                const float*  __restrict__ W2i, const float* __restrict__ b2i,
                const float*  __restrict__ W1e, const float* __restrict__ b1e,
                const float*  __restrict__ W2e, const float* __restrict__ b2e,
                float* __restrict__ out,            // (B, T)
                int T)
{
    extern __shared__ __align__(128) float4 xbuf[];    // RING * CELEMS float4
    __shared__ __align__(8) uint64_t mbar[RING];
    __shared__ float warp_tot[2][32];                  // double-buffered
    __shared__ float2 bnd[2];                          // (ts, f) carry, double-buffered

    const int b    = blockIdx.x;
    const int tid  = threadIdx.x;
    const int lane = tid & 31;
    const int warp = tid >> 5;
    constexpr int NW = NTHREADS / 32;                  // 6
    const unsigned FULL = 0xFFFFFFFFu;
    const long long rowbase = (long long)b * (long long)T;
    const int nchunks = (T + CELEMS - 1) / CELEMS;

    if (tid == 0) {
        #pragma unroll
        for (int r = 0; r < RING; r++)
            MBAR_INIT(smem_u32(&mbar[r]), 1);
    }
    __syncthreads();

    // prime the ring
    if (tid == 0) {
        const int prime = (nchunks < RING) ? nchunks : RING;
        for (int c = 0; c < prime; c++) {
            const int lim = min(CELEMS, T - c * CELEMS);
            const uint32_t nbytes = (uint32_t)lim * 16u;
            const uint32_t bar = smem_u32(&mbar[c]);
            MBAR_EXPECT_TX(bar, nbytes);
            BULK_G2S(smem_u32(&xbuf[c * CELEMS]),
                     (const void*)(X + rowbase + (long long)c * CELEMS),
                     nbytes, bar);
        }
    }

    // Per-batch scalars (overlaps with TMA flight)
    const float w1e0 = W1e[0], w1e1 = W1e[1];
    const float be1  = b1e[0];
    const float scale = SC[b * 4 + 1] / (3600.0f * SC[b * 4 + 0]);
    const float A  = scale * (1.0f + b2e[0]);  // f = I * (A + B*h)
    const float Bc = scale * W2e[0];

    float base = 0.0f;   // SOC_init + running cumsum carry (set at c==0)

    for (int c = 0; c < nchunks; c++) {
        const int slot = c % RING;
        mbar_wait_parity(smem_u32(&mbar[slot]), (uint32_t)((c / RING) & 1));

        const float4* xb = &xbuf[slot * CELEMS];
        const int lim = min(CELEMS, T - c * CELEMS);
        const int s = tid * 4;
        const int cb = c & 1;

        if (c == 0) {
            // SOC_init from t=0 features (broadcast LDS); exact softplus form
            float4 x0 = xb[0];
            float z0 = x0.y * W1i[0] + x0.z * W1i[1] + x0.w * W1i[2]
                     + SC[b * 4 + 2] * W1i[3] + b1i[0];
            float h0 = fmaxf(z0, 0.0f) + __logf(1.0f + __expf(-fabsf(z0)));
            base = SC[b * 4 + 3] * (1.0f + (h0 * W2i[0] + b2i[0]));
        }

        float i0 = 0.f, i1 = 0.f, i2 = 0.f, i3 = 0.f;
        float ts3 = 0.f, f3 = 0.f;             // last-elem (ts,f) for shfl / bnd

        if (s + 3 < lim) {
            float4 v0 = xb[s + 0];
            float4 v1 = xb[s + 1];
            float4 v2 = xb[s + 2];
            float4 v3 = xb[s + 3];
            float h0e = softplus_f(fmaf(v0.y, w1e0, fmaf(v0.z, w1e1, be1)));
            float h1e = softplus_f(fmaf(v1.y, w1e0, fmaf(v1.z, w1e1, be1)));
            float h2e = softplus_f(fmaf(v2.y, w1e0, fmaf(v2.z, w1e1, be1)));
            float h3e = softplus_f(fmaf(v3.y, w1e0, fmaf(v3.z, w1e1, be1)));
            float f0 = v0.y * fmaf(h0e, Bc, A);
            float f1 = v1.y * fmaf(h1e, Bc, A);
            float f2 = v2.y * fmaf(h2e, Bc, A);
            f3       = v3.y * fmaf(h3e, Bc, A);
            ts3 = v3.x;

            float pts = __shfl_up_sync(FULL, ts3, 1);
            float pf  = __shfl_up_sync(FULL, f3, 1);
            if (lane == 0) {
                if (s > 0) {                   // cross-warp boundary: recompute
                    float4 vp = xb[s - 1];
                    float hp = softplus_f(fmaf(vp.y, w1e0, fmaf(vp.z, w1e1, be1)));
                    pts = vp.x;
                    pf  = vp.y * fmaf(hp, Bc, A);
                } else if (c > 0) {            // chunk boundary carry
                    float2 bc = bnd[cb];       // written by chunk c-1 pre-its-barrier
                    pts = bc.x; pf = bc.y;
                }
            }
            if (c > 0 || s > 0 || lane > 0)    // global t==0 has no increment
                i0 = (v0.x - pts) * pf;
            i1 = (v1.x - v0.x) * f0;
            i2 = (v2.x - v1.x) * f1;
            i3 = (v3.x - v2.x) * f2;
        } else {
            // tail path (rare)
            float pts = 0.f, pf = 0.f;
            bool havep = false;
            if (s < lim && (s > 0 || c > 0)) {
                if (s > 0) {
                    float4 vp = xb[s - 1];
                    float hp = softplus_f(fmaf(vp.y, w1e0, fmaf(vp.z, w1e1, be1)));
                    pts = vp.x;
                    pf  = vp.y * fmaf(hp, Bc, A);
                } else { float2 bc = bnd[cb]; pts = bc.x; pf = bc.y; }
                havep = true;
            }
            float acc[4] = {0.f, 0.f, 0.f, 0.f};
            for (int j = 0; j < 4; j++) {
                const int t = s + j;
                if (t < lim) {
                    float4 v = xb[t];
                    if (havep) acc[j] = (v.x - pts) * pf;
                    float h = softplus_f(fmaf(v.y, w1e0, fmaf(v.z, w1e1, be1)));
                    pts = v.x;
                    pf  = v.y * fmaf(h, Bc, A);
                    havep = true;
                    ts3 = pts; f3 = pf;
                }
            }
            i0 = acc[0]; i1 = acc[1]; i2 = acc[2]; i3 = acc[3];
        }

        const float p0 = i0;
        const float p1 = p0 + i1;
        const float p2 = p1 + i2;
        const float run = p2 + i3;

        // warp-inclusive scan of per-thread totals
        float v = run;
        #pragma unroll
        for (int d = 1; d < 32; d <<= 1) {
            float o = __shfl_up_sync(FULL, v, d);
            if (lane >= d) v += o;
        }
        if (lane == 31) warp_tot[cb][warp] = v;
        // boundary carry for NEXT chunk (double-buffered; ordered by sync below)
        if (s == ((lim - 1) & ~3)) bnd[cb ^ 1] = make_float2(ts3, f3);

        __syncthreads();                       // single barrier per chunk

        // refill the freed slot with chunk c+RING ASAP (all xb reads pre-sync)
        if (tid == NTHREADS - 1 && c + RING < nchunks) {
            const int cn = c + RING;
            const int nlim = min(CELEMS, T - cn * CELEMS);
            const uint32_t nbytes = (uint32_t)nlim * 16u;
            const uint32_t bar = smem_u32(&mbar[slot]);
            MBAR_EXPECT_TX(bar, nbytes);
            BULK_G2S(smem_u32(&xbuf[slot * CELEMS]),
                     (const void*)(X + rowbase + (long long)cn * CELEMS),
                     nbytes, bar);
        }

        // every warp redundantly scans the NW warp totals (no 2nd sync)
        float w = (lane < NW) ? warp_tot[cb][lane] : 0.0f;
        #pragma unroll
        for (int d = 1; d < NW; d <<= 1) {
            float o = __shfl_up_sync(FULL, w, d);
            if (lane >= d) w += o;
        }
        const float warp_off = (warp > 0) ? __shfl_sync(FULL, w, warp - 1) : 0.0f;
        const float total    = __shfl_sync(FULL, w, NW - 1);

        const float excl = base + warp_off + (v - run);

        // ---- write out (STG.128) ----
        if (s + 3 < lim) {
            float4 ov;
            ov.x = excl + p0;
            ov.y = excl + p1;
            ov.z = excl + p2;
            ov.w = excl + run;
            *reinterpret_cast<float4*>(out + rowbase + c * CELEMS + s) = ov;
        } else {
            const float pv[4] = {p0, p1, p2, run};
            for (int j = 0; j < 4; j++)
                if (s + j < lim) out[rowbase + c * CELEMS + s + j] = excl + pv[j];
        }

        base += total;
    }
}

extern "C" void kernel_launch(void* const* d_in, const int* in_sizes, int n_in,
                              void* d_out, int out_size)
{
    const float4* X  = (const float4*)d_in[0];   // (B, T, 4) fp32
    const float* SC  = (const float*)d_in[1];    // (B, 4)
    const float* W1i = (const float*)d_in[2];
    const float* b1i = (const float*)d_in[3];
    const float* W2i = (const float*)d_in[4];
    const float* b2i = (const float*)d_in[5];
    const float* W1e = (const float*)d_in[6];
    const float* b1e = (const float*)d_in[7];
    const float* W2e = (const float*)d_in[8];
    const float* b2e = (const float*)d_in[9];
    float* out = (float*)d_out;

    const int B = in_sizes[1] / 4;               // SC is (B,4)
    const int T = in_sizes[0] / (B * 4);         // X is (B,T,4)

    constexpr int NTH = 192, CEL = 768, RING = 2;
    const int smem_bytes = RING * CEL * 16;      // 24 KB -> 8 CTAs/SM, single wave
    static bool attr_set = false;
    if (!attr_set) {
        cudaFuncSetAttribute(soc_kernel<NTH, CEL, RING>,
                             cudaFuncAttributeMaxDynamicSharedMemorySize, smem_bytes);
        attr_set = true;
    }
    soc_kernel<NTH, CEL, RING><<<B, NTH, smem_bytes>>>(
        X, SC, W1i, b1i, W2i, b2i, W1e, b1e, W2e, b2e, out, T);
}

// round 14
// speedup vs baseline: 1.0643x; 1.0072x over previous
#include <cuda_runtime.h>
#include <cuda_bf16.h>
#include <cstdint>

// fast softplus for small |x| (here |x| <~ 2, far from exp overflow at 88):
__device__ __forceinline__ float softplus_f(float x) {
    return __logf(1.0f + __expf(x));
}

__device__ __forceinline__ uint32_t smem_u32(const void* p) {
    return (uint32_t)__cvta_generic_to_shared(p);
}

#define MBAR_INIT(addr, cnt) \
    asm volatile("mbarrier.init.shared.b64 [%0], %1;" :: "r"(addr), "r"(cnt) : "memory")
#define MBAR_EXPECT_TX(addr, bytes) \
    asm volatile("mbarrier.arrive.expect_tx.shared.b64 _, [%0], %1;" :: "r"(addr), "r"(bytes) : "memory")
#define BULK_G2S(dst_smem, src_gmem, nbytes, bar) \
    asm volatile("cp.async.bulk.shared::cta.global.mbarrier::complete_tx::bytes [%0], [%1], %2, [%3];" \
                 :: "r"(dst_smem), "l"(src_gmem), "r"(nbytes), "r"(bar) : "memory")

__device__ __forceinline__ void mbar_wait_parity(uint32_t bar, uint32_t parity) {
    uint32_t done;
    asm volatile(
        "{\n\t.reg .pred p;\n\t"
        "mbarrier.try_wait.parity.acquire.cta.shared::cta.b64 p, [%1], %2;\n\t"
        "selp.b32 %0, 1, 0, p;\n\t}"
        : "=r"(done) : "r"(bar), "r"(parity) : "memory");
    while (!done) {
        asm volatile(
            "{\n\t.reg .pred p;\n\t"
            "mbarrier.try_wait.parity.acquire.cta.shared::cta.b64 p, [%1], %2, 0x989680;\n\t"
            "selp.b32 %0, 1, 0, p;\n\t}"
            : "=r"(done) : "r"(bar), "r"(parity) : "memory");
    }
}

// One CTA per batch row; 30KB smem/CTA -> 7 CTAs/SM, ALL 1024 CTAs
// co-resident (single wave) AND a 3-deep ring (2 chunks buffered ahead of
// compute -> mbar wait rarely blocks). 4 elems/thread per chunk, single
// __syncthreads per chunk.
template <int NTHREADS, int CELEMS, int RING>
__global__ __launch_bounds__(NTHREADS, 7)
void soc_kernel(const float4* __restrict__ X,       // (B, T, 4)
                const float*  __restrict__ SC,      // (B, 4)
                const float*  __restrict__ W1i, const float* __restrict__ b1i,
                const float*  __restrict__ W2i, const float* __restrict__ b2i,
                const float*  __restrict__ W1e, const float* __restrict__ b1e,
                const float*  __restrict__ W2e, const float* __restrict__ b2e,
                float* __restrict__ out,            // (B, T)
                int T)
{
    extern __shared__ __align__(128) float4 xbuf[];    // RING * CELEMS float4
    __shared__ __align__(8) uint64_t mbar[RING];
    __shared__ float warp_tot[2][32];                  // double-buffered
    __shared__ float2 bnd[2];                          // (ts, f) carry, double-buffered

    const int b    = blockIdx.x;
    const int tid  = threadIdx.x;
    const int lane = tid & 31;
    const int warp = tid >> 5;
    constexpr int NW = NTHREADS / 32;                  // 5
    const unsigned FULL = 0xFFFFFFFFu;
    const long long rowbase = (long long)b * (long long)T;
    const int nchunks = (T + CELEMS - 1) / CELEMS;

    if (tid == 0) {
        #pragma unroll
        for (int r = 0; r < RING; r++)
            MBAR_INIT(smem_u32(&mbar[r]), 1);
    }
    __syncthreads();

    // prime the full ring
    if (tid == 0) {
        const int prime = (nchunks < RING) ? nchunks : RING;
        for (int c = 0; c < prime; c++) {
            const int lim = min(CELEMS, T - c * CELEMS);
            const uint32_t nbytes = (uint32_t)lim * 16u;
            const uint32_t bar = smem_u32(&mbar[c]);
            MBAR_EXPECT_TX(bar, nbytes);
            BULK_G2S(smem_u32(&xbuf[c * CELEMS]),
                     (const void*)(X + rowbase + (long long)c * CELEMS),
                     nbytes, bar);
        }
    }

    // Per-batch scalars (overlaps with TMA flight)
    const float w1e0 = W1e[0], w1e1 = W1e[1];
    const float be1  = b1e[0];
    const float scale = SC[b * 4 + 1] / (3600.0f * SC[b * 4 + 0]);
    const float A  = scale * (1.0f + b2e[0]);  // f = I * (A + B*h)
    const float Bc = scale * W2e[0];

    float base = 0.0f;   // SOC_init + running cumsum carry (set at c==0)

    for (int c = 0; c < nchunks; c++) {
        const int slot = c % RING;
        const uint32_t parity = (uint32_t)((c / RING) & 1);
        mbar_wait_parity(smem_u32(&mbar[slot]), parity);

        const float4* xb = &xbuf[slot * CELEMS];
        const int lim = min(CELEMS, T - c * CELEMS);
        const int s = tid * 4;
        const int cb = c & 1;

        if (c == 0) {
            // SOC_init from t=0 features (broadcast LDS); exact softplus form
            float4 x0 = xb[0];
            float z0 = x0.y * W1i[0] + x0.z * W1i[1] + x0.w * W1i[2]
                     + SC[b * 4 + 2] * W1i[3] + b1i[0];
            float h0 = fmaxf(z0, 0.0f) + __logf(1.0f + __expf(-fabsf(z0)));
            base = SC[b * 4 + 3] * (1.0f + (h0 * W2i[0] + b2i[0]));
        }

        float i0 = 0.f, i1 = 0.f, i2 = 0.f, i3 = 0.f;
        float ts3 = 0.f, f3 = 0.f;             // last-elem (ts,f) for shfl / bnd

        if (s + 3 < lim) {
            float4 v0 = xb[s + 0];
            float4 v1 = xb[s + 1];
            float4 v2 = xb[s + 2];
            float4 v3 = xb[s + 3];
            float h0e = softplus_f(fmaf(v0.y, w1e0, fmaf(v0.z, w1e1, be1)));
            float h1e = softplus_f(fmaf(v1.y, w1e0, fmaf(v1.z, w1e1, be1)));
            float h2e = softplus_f(fmaf(v2.y, w1e0, fmaf(v2.z, w1e1, be1)));
            float h3e = softplus_f(fmaf(v3.y, w1e0, fmaf(v3.z, w1e1, be1)));
            float f0 = v0.y * fmaf(h0e, Bc, A);
            float f1 = v1.y * fmaf(h1e, Bc, A);
            float f2 = v2.y * fmaf(h2e, Bc, A);
            f3       = v3.y * fmaf(h3e, Bc, A);
            ts3 = v3.x;

            float pts = __shfl_up_sync(FULL, ts3, 1);
            float pf  = __shfl_up_sync(FULL, f3, 1);
            if (lane == 0) {
                if (s > 0) {                   // cross-warp boundary: recompute
                    float4 vp = xb[s - 1];
                    float hp = softplus_f(fmaf(vp.y, w1e0, fmaf(vp.z, w1e1, be1)));
                    pts = vp.x;
                    pf  = vp.y * fmaf(hp, Bc, A);
                } else if (c > 0) {            // chunk boundary carry
                    float2 bc = bnd[cb];       // written by chunk c-1 pre-its-barrier
                    pts = bc.x; pf = bc.y;
                }
            }
            if (c > 0 || s > 0 || lane > 0)    // global t==0 has no increment
                i0 = (v0.x - pts) * pf;
            i1 = (v1.x - v0.x) * f0;
            i2 = (v2.x - v1.x) * f1;
            i3 = (v3.x - v2.x) * f2;
        } else {
            // tail path (rare)
            float pts = 0.f, pf = 0.f;
            bool havep = false;
            if (s < lim && (s > 0 || c > 0)) {
                if (s > 0) {
                    float4 vp = xb[s - 1];
                    float hp = softplus_f(fmaf(vp.y, w1e0, fmaf(vp.z, w1e1, be1)));
                    pts = vp.x;
                    pf  = vp.y * fmaf(hp, Bc, A);
                } else { float2 bc = bnd[cb]; pts = bc.x; pf = bc.y; }
                havep = true;
            }
            float acc[4] = {0.f, 0.f, 0.f, 0.f};
            for (int j = 0; j < 4; j++) {
                const int t = s + j;
                if (t < lim) {
                    float4 v = xb[t];
                    if (havep) acc[j] = (v.x - pts) * pf;
                    float h = softplus_f(fmaf(v.y, w1e0, fmaf(v.z, w1e1, be1)));
                    pts = v.x;
                    pf  = v.y * fmaf(h, Bc, A);
                    havep = true;
                    ts3 = pts; f3 = pf;
                }
            }
            i0 = acc[0]; i1 = acc[1]; i2 = acc[2]; i3 = acc[3];
        }

        const float p0 = i0;
        const float p1 = p0 + i1;
        const float p2 = p1 + i2;
        const float run = p2 + i3;

        // warp-inclusive scan of per-thread totals
        float v = run;
        #pragma unroll
        for (int d = 1; d < 32; d <<= 1) {
            float o = __shfl_up_sync(FULL, v, d);
            if (lane >= d) v += o;
        }
        if (lane == 31) warp_tot[cb][warp] = v;
        // boundary carry for NEXT chunk (double-buffered; ordered by sync below)
        if (s == ((lim - 1) & ~3)) bnd[cb ^ 1] = make_float2(ts3, f3);

        __syncthreads();                       // single barrier per chunk

        // refill the freed slot with chunk c+RING ASAP (all xb reads pre-sync)
        if (tid == NTHREADS - 1 && c + RING < nchunks) {
            const int cn = c + RING;
            const int nlim = min(CELEMS, T - cn * CELEMS);
            const uint32_t nbytes = (uint32_t)nlim * 16u;
            const uint32_t bar = smem_u32(&mbar[slot]);
            MBAR_EXPECT_TX(bar, nbytes);
            BULK_G2S(smem_u32(&xbuf[slot * CELEMS]),
                     (const void*)(X + rowbase + (long long)cn * CELEMS),
                     nbytes, bar);
        }

        // every warp redundantly scans the NW warp totals (no 2nd sync)
        float w = (lane < NW) ? warp_tot[cb][lane] : 0.0f;
        #pragma unroll
        for (int d = 1; d < 8; d <<= 1) {      // covers NW=5
            float o = __shfl_up_sync(FULL, w, d);
            if (lane >= d) w += o;
        }
        const float warp_off = (warp > 0) ? __shfl_sync(FULL, w, warp - 1) : 0.0f;
        const float total    = __shfl_sync(FULL, w, NW - 1);

        const float excl = base + warp_off + (v - run);

        // ---- write out (STG.128) ----
        if (s + 3 < lim) {
            float4 ov;
            ov.x = excl + p0;
            ov.y = excl + p1;
            ov.z = excl + p2;
            ov.w = excl + run;
            *reinterpret_cast<float4*>(out + rowbase + c * CELEMS + s) = ov;
        } else {
            const float pv[4] = {p0, p1, p2, run};
            for (int j = 0; j < 4; j++)
                if (s + j < lim) out[rowbase + c * CELEMS + s + j] = excl + pv[j];
        }

        base += total;
    }
}

extern "C" void kernel_launch(void* const* d_in, const int* in_sizes, int n_in,
                              void* d_out, int out_size)
{
    const float4* X  = (const float4*)d_in[0];   // (B, T, 4) fp32
    const float* SC  = (const float*)d_in[1];    // (B, 4)
    const float* W1i = (const float*)d_in[2];
    const float* b1i = (const float*)d_in[3];
    const float* W2i = (const float*)d_in[4];
    const float* b2i = (const float*)d_in[5];
    const float* W1e = (const float*)d_in[6];
    const float* b1e = (const float*)d_in[7];
    const float* W2e = (const float*)d_in[8];
    const float* b2e = (const float*)d_in[9];
    float* out = (float*)d_out;

    const int B = in_sizes[1] / 4;               // SC is (B,4)
    const int T = in_sizes[0] / (B * 4);         // X is (B,T,4)

    constexpr int NTH = 160, CEL = 640, RING = 3;
    const int smem_bytes = RING * CEL * 16;      // 30 KB -> 7 CTAs/SM, single wave
    static bool attr_set = false;
    if (!attr_set) {
        cudaFuncSetAttribute(soc_kernel<NTH, CEL, RING>,
                             cudaFuncAttributeMaxDynamicSharedMemorySize, smem_bytes);
        attr_set = true;
    }
    soc_kernel<NTH, CEL, RING><<<B, NTH, smem_bytes>>>(
        X, SC, W1i, b1i, W2i, b2i, W1e, b1e, W2e, b2e, out, T);
}

// round 15
// speedup vs baseline: 1.0760x; 1.0110x over previous
#include <cuda_runtime.h>
#include <cuda_bf16.h>
#include <cstdint>

// fast softplus for small |x| (here |x| <~ 2, far from exp overflow at 88):
__device__ __forceinline__ float softplus_f(float x) {
    return __logf(1.0f + __expf(x));
}

__device__ __forceinline__ uint32_t smem_u32(const void* p) {
    return (uint32_t)__cvta_generic_to_shared(p);
}

#define MBAR_INIT(addr, cnt) \
    asm volatile("mbarrier.init.shared.b64 [%0], %1;" :: "r"(addr), "r"(cnt) : "memory")
#define MBAR_EXPECT_TX(addr, bytes) \
    asm volatile("mbarrier.arrive.expect_tx.shared.b64 _, [%0], %1;" :: "r"(addr), "r"(bytes) : "memory")
#define BULK_G2S(dst_smem, src_gmem, nbytes, bar) \
    asm volatile("cp.async.bulk.shared::cta.global.mbarrier::complete_tx::bytes [%0], [%1], %2, [%3];" \
                 :: "r"(dst_smem), "l"(src_gmem), "r"(nbytes), "r"(bar) : "memory")

__device__ __forceinline__ void mbar_wait_parity(uint32_t bar, uint32_t parity) {
    uint32_t done;
    asm volatile(
        "{\n\t.reg .pred p;\n\t"
        "mbarrier.try_wait.parity.acquire.cta.shared::cta.b64 p, [%1], %2;\n\t"
        "selp.b32 %0, 1, 0, p;\n\t}"
        : "=r"(done) : "r"(bar), "r"(parity) : "memory");
    while (!done) {
        asm volatile(
            "{\n\t.reg .pred p;\n\t"
            "mbarrier.try_wait.parity.acquire.cta.shared::cta.b64 p, [%1], %2, 0x989680;\n\t"
            "selp.b32 %0, 1, 0, p;\n\t}"
            : "=r"(done) : "r"(bar), "r"(parity) : "memory");
    }
}

// One CTA per batch row, 7 CTAs/SM, single wave. Two-phase chunk pipeline:
// Phase A: coalesced (conflict-free) LDS of x, compute incr[e], coalesced STS.
// Phase B: conflict-free LDS.128 of incr (16B lane stride), prefix + block
// scan, STG.128. TMA refill issued right after the A->B barrier so it
// overlaps phase B.
template <int NTHREADS, int CELEMS, int RING>
__global__ __launch_bounds__(NTHREADS, 7)
void soc_kernel(const float4* __restrict__ X,       // (B, T, 4)
                const float*  __restrict__ SC,      // (B, 4)
                const float*  __restrict__ W1i, const float* __restrict__ b1i,
                const float*  __restrict__ W2i, const float* __restrict__ b2i,
                const float*  __restrict__ W1e, const float* __restrict__ b1e,
                const float*  __restrict__ W2e, const float* __restrict__ b2e,
                float* __restrict__ out,            // (B, T)
                int T)
{
    extern __shared__ __align__(128) float4 xbuf[];    // RING*CELEMS float4 + CELEMS floats
    float* incr = reinterpret_cast<float*>(xbuf + RING * CELEMS);
    __shared__ __align__(8) uint64_t mbar[RING];
    __shared__ float warp_tot[2][32];                  // double-buffered
    __shared__ float2 bnd[2];                          // (ts, f) carry, double-buffered

    const int b    = blockIdx.x;
    const int tid  = threadIdx.x;
    const int lane = tid & 31;
    const int warp = tid >> 5;
    constexpr int NW = NTHREADS / 32;                  // 6
    constexpr int NJ = CELEMS / NTHREADS;              // 4
    const unsigned FULL = 0xFFFFFFFFu;
    const long long rowbase = (long long)b * (long long)T;
    const int nchunks = (T + CELEMS - 1) / CELEMS;

    if (tid == 0) {
        #pragma unroll
        for (int r = 0; r < RING; r++)
            MBAR_INIT(smem_u32(&mbar[r]), 1);
    }
    __syncthreads();

    // prime the ring
    if (tid == 0) {
        const int prime = (nchunks < RING) ? nchunks : RING;
        for (int c = 0; c < prime; c++) {
            const int lim = min(CELEMS, T - c * CELEMS);
            const uint32_t nbytes = (uint32_t)lim * 16u;
            const uint32_t bar = smem_u32(&mbar[c]);
            MBAR_EXPECT_TX(bar, nbytes);
            BULK_G2S(smem_u32(&xbuf[c * CELEMS]),
                     (const void*)(X + rowbase + (long long)c * CELEMS),
                     nbytes, bar);
        }
    }

    // Per-batch scalars (overlaps with TMA flight)
    const float w1e0 = W1e[0], w1e1 = W1e[1];
    const float be1  = b1e[0];
    const float scale = SC[b * 4 + 1] / (3600.0f * SC[b * 4 + 0]);
    const float A  = scale * (1.0f + b2e[0]);  // f = I * (A + B*h)
    const float Bc = scale * W2e[0];

    float base = 0.0f;   // SOC_init + running cumsum carry (set at c==0)

    for (int c = 0; c < nchunks; c++) {
        const int slot = c % RING;
        mbar_wait_parity(smem_u32(&mbar[slot]), (uint32_t)((c / RING) & 1));

        const float4* xb = &xbuf[slot * CELEMS];
        const int lim = min(CELEMS, T - c * CELEMS);
        const int cb = c & 1;

        if (c == 0) {
            // SOC_init from t=0 features (broadcast LDS); exact softplus form
            float4 x0 = xb[0];
            float z0 = x0.y * W1i[0] + x0.z * W1i[1] + x0.w * W1i[2]
                     + SC[b * 4 + 2] * W1i[3] + b1i[0];
            float h0 = fmaxf(z0, 0.0f) + __logf(1.0f + __expf(-fabsf(z0)));
            base = SC[b * 4 + 3] * (1.0f + (h0 * W2i[0] + b2i[0]));
        }

        // ---- Phase A: coalesced LDS, compute incr, coalesced STS ----
        #pragma unroll
        for (int j = 0; j < NJ; j++) {
            const int e = j * NTHREADS + tid;
            if (e < lim) {
                float4 v = xb[e];                       // conflict-free LDS.128
                float ts = v.x;
                float h  = softplus_f(fmaf(v.y, w1e0, fmaf(v.z, w1e1, be1)));
                float f  = v.y * fmaf(h, Bc, A);

                float pts = __shfl_up_sync(FULL, ts, 1);
                float pf  = __shfl_up_sync(FULL, f, 1);
                if (lane == 0) {
                    if (e > 0) {                        // warp boundary: recompute
                        float4 vp = xb[e - 1];
                        float hp = softplus_f(fmaf(vp.y, w1e0, fmaf(vp.z, w1e1, be1)));
                        pts = vp.x;
                        pf  = vp.y * fmaf(hp, Bc, A);
                    } else if (c > 0) {                 // chunk boundary carry
                        float2 bc = bnd[cb];
                        pts = bc.x; pf = bc.y;
                    }
                }
                float ic = (c == 0 && e == 0) ? 0.0f : (ts - pts) * pf;
                incr[e] = ic;                           // coalesced STS.32
                if (e == lim - 1) bnd[cb ^ 1] = make_float2(ts, f);
            }
        }
        __syncthreads();                                // barrier 1: incr ready, xb consumed

        // refill the freed slot NOW (overlaps phase B)
        if (tid == NTHREADS - 1 && c + RING < nchunks) {
            const int cn = c + RING;
            const int nlim = min(CELEMS, T - cn * CELEMS);
            const uint32_t nbytes = (uint32_t)nlim * 16u;
            const uint32_t bar = smem_u32(&mbar[slot]);
            MBAR_EXPECT_TX(bar, nbytes);
            BULK_G2S(smem_u32(&xbuf[slot * CELEMS]),
                     (const void*)(X + rowbase + (long long)cn * CELEMS),
                     nbytes, bar);
        }

        // ---- Phase B: conflict-free LDS.128 of incr, prefix + block scan ----
        const int s = tid * 4;
        float p0 = 0.f, p1 = 0.f, p2 = 0.f, run = 0.f;
        if (s + 3 < lim) {
            float4 iv = *reinterpret_cast<const float4*>(incr + s);  // 16B stride: conflict-free
            p0 = iv.x;
            p1 = p0 + iv.y;
            p2 = p1 + iv.z;
            run = p2 + iv.w;
        } else if (s < lim) {
            float acc = 0.f;
            float pv[4] = {0.f, 0.f, 0.f, 0.f};
            for (int j = 0; j < 4; j++) {
                if (s + j < lim) { acc += incr[s + j]; pv[j] = acc; }
            }
            p0 = pv[0]; p1 = pv[1]; p2 = pv[2]; run = acc;
        }

        // warp-inclusive scan of per-thread totals
        float v = run;
        #pragma unroll
        for (int d = 1; d < 32; d <<= 1) {
            float o = __shfl_up_sync(FULL, v, d);
            if (lane >= d) v += o;
        }
        if (lane == 31) warp_tot[cb][warp] = v;
        __syncthreads();                                // barrier 2

        // every warp redundantly scans the NW warp totals (no 3rd sync)
        float w = (lane < NW) ? warp_tot[cb][lane] : 0.0f;
        #pragma unroll
        for (int d = 1; d < 8; d <<= 1) {               // covers NW=6
            float o = __shfl_up_sync(FULL, w, d);
            if (lane >= d) w += o;
        }
        const float warp_off = (warp > 0) ? __shfl_sync(FULL, w, warp - 1) : 0.0f;
        const float total    = __shfl_sync(FULL, w, NW - 1);

        const float excl = base + warp_off + (v - run);

        // ---- write out (STG.128) ----
        if (s + 3 < lim) {
            float4 ov;
            ov.x = excl + p0;
            ov.y = excl + p1;
            ov.z = excl + p2;
            ov.w = excl + run;
            *reinterpret_cast<float4*>(out + rowbase + c * CELEMS + s) = ov;
        } else if (s < lim) {
            const float pv[4] = {p0, p1, p2, run};
            for (int j = 0; j < 4; j++)
                if (s + j < lim) out[rowbase + c * CELEMS + s + j] = excl + pv[j];
        }

        base += total;
    }
}

extern "C" void kernel_launch(void* const* d_in, const int* in_sizes, int n_in,
                              void* d_out, int out_size)
{
    const float4* X  = (const float4*)d_in[0];   // (B, T, 4) fp32
    const float* SC  = (const float*)d_in[1];    // (B, 4)
    const float* W1i = (const float*)d_in[2];
    const float* b1i = (const float*)d_in[3];
    const float* W2i = (const float*)d_in[4];
    const float* b2i = (const float*)d_in[5];
    const float* W1e = (const float*)d_in[6];
    const float* b1e = (const float*)d_in[7];
    const float* W2e = (const float*)d_in[8];
    const float* b2e = (const float*)d_in[9];
    float* out = (float*)d_out;

    const int B = in_sizes[1] / 4;               // SC is (B,4)
    const int T = in_sizes[0] / (B * 4);         // X is (B,T,4)

    constexpr int NTH = 192, CEL = 768, RING = 2;
    const int smem_bytes = RING * CEL * 16 + CEL * 4;  // 24KB x + 3KB incr
    static bool attr_set = false;
    if (!attr_set) {
        cudaFuncSetAttribute(soc_kernel<NTH, CEL, RING>,
                             cudaFuncAttributeMaxDynamicSharedMemorySize, smem_bytes);
        attr_set = true;
    }
    soc_kernel<NTH, CEL, RING><<<B, NTH, smem_bytes>>>(
        X, SC, W1i, b1i, W2i, b2i, W1e, b1e, W2e, b2e, out, T);
}